// round 4
// baseline (speedup 1.0000x reference)
#include <cuda_runtime.h>
#include <cuda_bf16.h>

#define NB   64      // batch
#define NS   6       // strings
#define NT   2000    // frames
#define NC   25      // classes
#define ROWS_PER_S   (NB * NT)        // 128000
#define BLOCK        256
#define FRET_BLOCKS  (ROWS_PER_S / BLOCK)   // 500 (exact)
#define PLANE        (NT * NC)        // 50000 floats per (b) within one s
#define BSTRIDE      (NS * NT * NC)   // 300000 floats per b in full tensor
#define COLS         (NS * NT)        // 12000 onset columns

// Scratch (no allocation allowed in kernel_launch)
__device__ float g_fret_part[NS * FRET_BLOCKS];
__device__ float g_onset_st[COLS];

// ---------------------------------------------------------------------------
// Fret CE kernel: grid = (500, 6). Each block handles 256 rows (b*NT+t) of one
// string s. Rows are staged into SMEM via fully coalesced loads (the 25-float
// rows are contiguous across t within a fixed (b,s) plane), then each thread
// computes one row's NLL from SMEM (stride-25 = bank-conflict-free).
// ---------------------------------------------------------------------------
__global__ __launch_bounds__(BLOCK) void fret_kernel(
    const float* __restrict__ of,   // [B,S,T,C]
    const int*   __restrict__ tf)   // [B,S,T]
{
    __shared__ float tile[BLOCK * NC];   // 25.6 KB
    __shared__ float wred[BLOCK / 32];

    const int s  = blockIdx.y;
    const int r0 = blockIdx.x * BLOCK;   // base row within this s-plane (row = b*NT + t)

    // ---- coalesced stage: local flat offset p = row*25 + c = b*PLANE + t*25 + c
    // global index g = p + b*(BSTRIDE - PLANE) + s*PLANE
    const int p0 = r0 * NC;
    for (int k = threadIdx.x; k < BLOCK * NC; k += BLOCK) {
        int p = p0 + k;
        int b = p / PLANE;
        int g = p + b * (BSTRIDE - PLANE) + s * PLANE;
        tile[k] = of[g];
    }
    __syncthreads();

    // ---- per-row CE
    const int   row = r0 + threadIdx.x;
    const float* x  = &tile[threadIdx.x * NC];

    float v[NC];
    #pragma unroll
    for (int c = 0; c < NC; c++) v[c] = x[c];

    float m = v[0];
    #pragma unroll
    for (int c = 1; c < NC; c++) m = fmaxf(m, v[c]);

    float sum = 0.f;
    #pragma unroll
    for (int c = 0; c < NC; c++) sum += __expf(v[c] - m);

    const int b   = row / NT;
    const int t   = row - b * NT;
    const int tgt = tf[(b * NS + s) * NT + t];
    const float xt = x[tgt];                 // dynamic gather from SMEM (not regs)

    float nll = __logf(sum) + m - xt;

    // ---- block reduction (shuffle + one SMEM round)
    #pragma unroll
    for (int o = 16; o > 0; o >>= 1)
        nll += __shfl_down_sync(0xFFFFFFFFu, nll, o);
    const int wid = threadIdx.x >> 5;
    const int lid = threadIdx.x & 31;
    if (lid == 0) wred[wid] = nll;
    __syncthreads();
    if (threadIdx.x == 0) {
        float a = 0.f;
        #pragma unroll
        for (int w = 0; w < BLOCK / 32; w++) a += wred[w];
        g_fret_part[s * FRET_BLOCKS + blockIdx.x] = a;
    }
}

// ---------------------------------------------------------------------------
// Onset kernel: one thread per (s,t) column, softmax over the batch axis.
// Consecutive threads -> consecutive t -> coalesced (stride COLS over b).
// ---------------------------------------------------------------------------
__global__ __launch_bounds__(256) void onset_kernel(
    const float* __restrict__ oo,   // [B,S,T]
    const float* __restrict__ to)   // [B,S,T]
{
    const int col = blockIdx.x * blockDim.x + threadIdx.x;
    if (col >= COLS) return;

    float m = -3.402823466e+38f;
    #pragma unroll 4
    for (int b = 0; b < NB; b++)
        m = fmaxf(m, oo[b * COLS + col]);

    float sum = 0.f, tsum = 0.f, txsum = 0.f;
    #pragma unroll 4
    for (int b = 0; b < NB; b++) {
        float xv = oo[b * COLS + col];
        float tg = to[b * COLS + col];
        sum   += __expf(xv - m);
        tsum  += tg;
        txsum += tg * xv;
    }
    // on_st = -sum_b tg*(x - lse) = lse*tsum - txsum
    g_onset_st[col] = (__logf(sum) + m) * tsum - txsum;
}

// ---------------------------------------------------------------------------
// Final deterministic reduction: 6 warps, warp s reduces its string's fret
// partials (500) and onset per-frame losses (2000); thread 0 assembles output.
// Output layout (15 fp32): loss, fret_loss, onset_loss, fret_string[6],
// onset_string[6].
// ---------------------------------------------------------------------------
__global__ void final_kernel(float* __restrict__ out, int out_size)
{
    __shared__ float fs[NS], os_[NS];
    const int w   = threadIdx.x >> 5;
    const int lid = threadIdx.x & 31;

    if (w < NS) {
        float a = 0.f;
        for (int i = lid; i < FRET_BLOCKS; i += 32)
            a += g_fret_part[w * FRET_BLOCKS + i];
        #pragma unroll
        for (int o = 16; o > 0; o >>= 1)
            a += __shfl_down_sync(0xFFFFFFFFu, a, o);

        float b = 0.f;
        for (int i = lid; i < NT; i += 32)
            b += g_onset_st[w * NT + i];
        #pragma unroll
        for (int o = 16; o > 0; o >>= 1)
            b += __shfl_down_sync(0xFFFFFFFFu, b, o);

        if (lid == 0) {
            fs[w]  = a * (1.0f / NB);   // mean over batch
            os_[w] = b;
        }
    }
    __syncthreads();

    if (threadIdx.x == 0) {
        float fl = 0.f, ol = 0.f;
        #pragma unroll
        for (int s = 0; s < NS; s++) { fl += fs[s]; ol += os_[s]; }
        float loss = 0.5f * fl + 0.5f * ol;
        if (0  < out_size) out[0] = loss;
        if (1  < out_size) out[1] = fl;
        if (2  < out_size) out[2] = ol;
        #pragma unroll
        for (int s = 0; s < NS; s++) {
            if (3 + s < out_size) out[3 + s] = fs[s];
            if (9 + s < out_size) out[9 + s] = os_[s];
        }
    }
    // zero any padding beyond the 15 semantic outputs (d_out is poisoned)
    for (int i = 15 + (int)threadIdx.x; i < out_size; i += (int)blockDim.x)
        out[i] = 0.f;
}

extern "C" void kernel_launch(void* const* d_in, const int* in_sizes, int n_in,
                              void* d_out, int out_size) {
    const float* output_fret  = (const float*)d_in[0];
    const int*   target_fret  = (const int*)  d_in[1];
    const float* output_onset = (const float*)d_in[2];
    const float* target_onset = (const float*)d_in[3];
    float* out = (float*)d_out;

    fret_kernel <<<dim3(FRET_BLOCKS, NS), BLOCK>>>(output_fret, target_fret);
    onset_kernel<<<(COLS + 255) / 256, 256>>>(output_onset, target_onset);
    final_kernel<<<1, 192>>>(out, out_size);
}

// round 5
// speedup vs baseline: 1.3673x; 1.3673x over previous
#include <cuda_runtime.h>
#include <cuda_bf16.h>
#include <cstdint>

#define NB   64
#define NS   6
#define NT   2000
#define NC   25
#define BLOCK        256
#define TILE_ROWS    256
#define TILES_PER_S  500                 // 128000/256
#define TILES_PER_BLOCK 2
#define FGRID_X      (TILES_PER_S / TILES_PER_BLOCK)   // 250
#define PLANE        (NT * NC)           // 50000
#define BSTRIDE      (NS * NT * NC)      // 300000
#define COLS         (NS * NT)           // 12000
#define TILE_F4      (TILE_ROWS * NC / 4)  // 1600
#define TILE_BYTES   (TILE_ROWS * NC * 4)  // 25600

__device__ float g_fret_part[NS * TILES_PER_S];
__device__ float g_onset_st[COLS];

__device__ __forceinline__ uint32_t s2u(const void* p) {
    uint32_t a;
    asm("{ .reg .u64 t; cvta.to.shared.u64 t, %1; cvt.u32.u64 %0, t; }"
        : "=r"(a) : "l"(p));
    return a;
}
__device__ __forceinline__ void cp16(uint32_t dst, const void* src) {
    asm volatile("cp.async.cg.shared.global [%0], [%1], 16;\n"
                 :: "r"(dst), "l"(src));
}

// ---------------------------------------------------------------------------
// Fret CE: grid (250, 6), 256 threads. Each block pipelines 2 tiles of 256
// rows via cp.async double buffering: both tiles' loads are issued up-front
// (~51KB in flight per block), tile1 latency hides under tile0 compute.
// ---------------------------------------------------------------------------
__device__ __forceinline__ void stage_tile(const float* __restrict__ of,
                                           int s, int r0, uint32_t sbase) {
    const int p0 = r0 * NC;           // float offset within the s-plane
    #pragma unroll
    for (int j = 0; j < 7; j++) {
        int q = threadIdx.x + j * BLOCK;      // float4 index within tile
        if (q < TILE_F4) {
            int p = p0 + q * 4;
            int b = p / PLANE;                // constant across the float4
            const float* g = of + (p + b * (BSTRIDE - PLANE) + s * PLANE);
            cp16(sbase + q * 16, g);
        }
    }
    asm volatile("cp.async.commit_group;\n");
}

extern __shared__ float fret_buf[];   // 2 * TILE_ROWS * NC floats

__global__ __launch_bounds__(BLOCK) void fret_kernel(
    const float* __restrict__ of,     // [B,S,T,C]
    const int*   __restrict__ tf)     // [B,S,T]
{
    __shared__ float wred[BLOCK / 32];

    const int s     = blockIdx.y;
    const int tile0 = blockIdx.x * TILES_PER_BLOCK;
    const uint32_t sb0 = s2u(fret_buf);
    const uint32_t sb1 = sb0 + TILE_BYTES;

    stage_tile(of, s, (tile0 + 0) * TILE_ROWS, sb0);
    stage_tile(of, s, (tile0 + 1) * TILE_ROWS, sb1);

    #pragma unroll
    for (int it = 0; it < TILES_PER_BLOCK; it++) {
        const int r0  = (tile0 + it) * TILE_ROWS;
        const int row = r0 + threadIdx.x;
        const int b   = row / NT;
        const int t   = row - b * NT;
        const int tgt = tf[(b * NS + s) * NT + t];   // LDG issued before wait

        if (it == 0) asm volatile("cp.async.wait_group 1;\n" ::: "memory");
        else         asm volatile("cp.async.wait_group 0;\n" ::: "memory");
        __syncthreads();

        const float* x = fret_buf + it * (TILE_ROWS * NC) + threadIdx.x * NC;

        float v[NC];
        #pragma unroll
        for (int c = 0; c < NC; c++) v[c] = x[c];

        float m = v[0];
        #pragma unroll
        for (int c = 1; c < NC; c++) m = fmaxf(m, v[c]);

        float sum = 0.f;
        #pragma unroll
        for (int c = 0; c < NC; c++) sum += __expf(v[c] - m);

        float nll = __logf(sum) + m - x[tgt];

        #pragma unroll
        for (int o = 16; o > 0; o >>= 1)
            nll += __shfl_down_sync(0xFFFFFFFFu, nll, o);
        const int wid = threadIdx.x >> 5;
        const int lid = threadIdx.x & 31;
        if (lid == 0) wred[wid] = nll;
        __syncthreads();
        if (threadIdx.x == 0) {
            float a = 0.f;
            #pragma unroll
            for (int w = 0; w < BLOCK / 32; w++) a += wred[w];
            g_fret_part[s * TILES_PER_S + tile0 + it] = a;
        }
    }
}

// ---------------------------------------------------------------------------
// Onset: softmax over batch. 250 blocks x 256 threads; each block stages a
// [64 x 48] tile of both arrays (coalesced rows), then 4 threads per column
// reduce 16 batch entries each, merged with shuffles.
// ---------------------------------------------------------------------------
#define OC 48     // columns per block; 12000/48 = 250 exact
__global__ __launch_bounds__(256) void onset_kernel(
    const float* __restrict__ oo,     // [B,S,T]
    const float* __restrict__ to)     // [B,S,T]
{
    __shared__ float so[NB * OC];
    __shared__ float st[NB * OC];
    const int col0 = blockIdx.x * OC;

    for (int i = threadIdx.x; i < NB * OC; i += 256) {
        int b = i / OC, c = i - b * OC;
        int g = b * COLS + col0 + c;
        so[i] = oo[g];
        st[i] = to[g];
    }
    __syncthreads();

    if (threadIdx.x < 4 * OC) {
        const int c = threadIdx.x >> 2;       // column 0..47
        const int q = threadIdx.x & 3;        // batch quarter

        float m = -3.402823466e+38f;
        #pragma unroll
        for (int i = 0; i < 16; i++)
            m = fmaxf(m, so[(q * 16 + i) * OC + c]);
        m = fmaxf(m, __shfl_xor_sync(0xFFFFFFFFu, m, 1));
        m = fmaxf(m, __shfl_xor_sync(0xFFFFFFFFu, m, 2));

        float sum = 0.f, ts = 0.f, txs = 0.f;
        #pragma unroll
        for (int i = 0; i < 16; i++) {
            float xv = so[(q * 16 + i) * OC + c];
            float tg = st[(q * 16 + i) * OC + c];
            sum += __expf(xv - m);
            ts  += tg;
            txs += tg * xv;
        }
        sum += __shfl_xor_sync(0xFFFFFFFFu, sum, 1);
        sum += __shfl_xor_sync(0xFFFFFFFFu, sum, 2);
        ts  += __shfl_xor_sync(0xFFFFFFFFu, ts, 1);
        ts  += __shfl_xor_sync(0xFFFFFFFFu, ts, 2);
        txs += __shfl_xor_sync(0xFFFFFFFFu, txs, 1);
        txs += __shfl_xor_sync(0xFFFFFFFFu, txs, 2);

        if (q == 0)
            g_onset_st[col0 + c] = (__logf(sum) + m) * ts - txs;
    }
}

// ---------------------------------------------------------------------------
// Final deterministic reduction: warp s reduces its string's partials.
// Output (15 fp32): loss, fret_loss, onset_loss, fret_string[6], onset_string[6].
// ---------------------------------------------------------------------------
__global__ void final_kernel(float* __restrict__ out, int out_size)
{
    __shared__ float fs[NS], os_[NS];
    const int w   = threadIdx.x >> 5;
    const int lid = threadIdx.x & 31;

    if (w < NS) {
        float a = 0.f;
        for (int i = lid; i < TILES_PER_S; i += 32)
            a += g_fret_part[w * TILES_PER_S + i];
        #pragma unroll
        for (int o = 16; o > 0; o >>= 1)
            a += __shfl_down_sync(0xFFFFFFFFu, a, o);

        float b = 0.f;
        for (int i = lid; i < NT; i += 32)
            b += g_onset_st[w * NT + i];
        #pragma unroll
        for (int o = 16; o > 0; o >>= 1)
            b += __shfl_down_sync(0xFFFFFFFFu, b, o);

        if (lid == 0) {
            fs[w]  = a * (1.0f / NB);
            os_[w] = b;
        }
    }
    __syncthreads();

    if (threadIdx.x == 0) {
        float fl = 0.f, ol = 0.f;
        #pragma unroll
        for (int s = 0; s < NS; s++) { fl += fs[s]; ol += os_[s]; }
        float loss = 0.5f * fl + 0.5f * ol;
        if (0 < out_size) out[0] = loss;
        if (1 < out_size) out[1] = fl;
        if (2 < out_size) out[2] = ol;
        #pragma unroll
        for (int s = 0; s < NS; s++) {
            if (3 + s < out_size) out[3 + s] = fs[s];
            if (9 + s < out_size) out[9 + s] = os_[s];
        }
    }
    for (int i = 15 + (int)threadIdx.x; i < out_size; i += (int)blockDim.x)
        out[i] = 0.f;
}

extern "C" void kernel_launch(void* const* d_in, const int* in_sizes, int n_in,
                              void* d_out, int out_size) {
    const float* output_fret  = (const float*)d_in[0];
    const int*   target_fret  = (const int*)  d_in[1];
    const float* output_onset = (const float*)d_in[2];
    const float* target_onset = (const float*)d_in[3];
    float* out = (float*)d_out;

    cudaFuncSetAttribute(fret_kernel,
                         cudaFuncAttributeMaxDynamicSharedMemorySize,
                         2 * TILE_BYTES);

    fret_kernel <<<dim3(FGRID_X, NS), BLOCK, 2 * TILE_BYTES>>>(output_fret, target_fret);
    onset_kernel<<<COLS / OC, 256>>>(output_onset, target_onset);
    final_kernel<<<1, 192>>>(out, out_size);
}